// round 12
// baseline (speedup 1.0000x reference)
#include <cuda_runtime.h>
#include <cstdint>

// AttentionBlock fused gate kernel — quarter-offset 4-stream ILP=4 (MLP=8)
// with L2::256B fetch granules + evict_first streaming policy on loads and
// stores.
// Inputs: xatt[B*L*C], xsaut[B*L*C], W_act[C], b_act[1], W_saut[C], b_saut[1], W2[1], b2[1]
// Output: out[B*L] fp32.  B=64, L=16384, C=64 -> n_pos = 1,048,576 (q = 262,144).
//
// 16 lanes handle positions (k, k+q, k+2q, k+3q): 8 front-batched independent
// LDG.128 per thread, 8 sequential address streams, 256B L2 granules,
// evict_first (stream-once data).

#define NEG_SLOPE 0.3f

__device__ __forceinline__ float4 ldg_stream(const float4* p, uint64_t pol) {
    float4 v;
    asm volatile("ld.global.nc.L2::cache_hint.L2::256B.v4.f32 {%0,%1,%2,%3}, [%4], %5;"
                 : "=f"(v.x), "=f"(v.y), "=f"(v.z), "=f"(v.w)
                 : "l"(p), "l"(pol));
    return v;
}
__device__ __forceinline__ void stg_stream(float* p, float v, uint64_t pol) {
    asm volatile("st.global.L2::cache_hint.f32 [%0], %1, %2;"
                 :: "l"(p), "f"(v), "l"(pol) : "memory");
}

__global__ __launch_bounds__(256) void attn_gate_kernel(
    const float* __restrict__ xatt,
    const float* __restrict__ xsaut,
    const float* __restrict__ W_act,
    const float* __restrict__ b_act,
    const float* __restrict__ W_saut,
    const float* __restrict__ b_saut,
    const float* __restrict__ W2,
    const float* __restrict__ b2,
    float* __restrict__ out,
    int q)                                  // n_pos / 4
{
    const int gtid   = blockIdx.x * blockDim.x + threadIdx.x;
    const int k      = gtid >> 4;           // 16 lanes per position group
    const int lane16 = gtid & 15;
    if (k >= q) return;

    uint64_t pol;
    asm("createpolicy.fractional.L2::evict_first.b64 %0, 1.0;" : "=l"(pol));

    const float4 wa = __ldg(reinterpret_cast<const float4*>(W_act)  + lane16);
    const float4 ws = __ldg(reinterpret_cast<const float4*>(W_saut) + lane16);

    const float4* __restrict__ xa4 = reinterpret_cast<const float4*>(xatt);
    const float4* __restrict__ xs4 = reinterpret_cast<const float4*>(xsaut);

    const size_t b0     = (size_t)k * 16 + lane16;
    const size_t stream = (size_t)q * 16;

    // 8 independent global loads, front-batched (MLP=8), 8 address streams
    const float4 a0 = ldg_stream(xa4 + b0,              pol);
    const float4 a1 = ldg_stream(xa4 + b0 +     stream, pol);
    const float4 a2 = ldg_stream(xa4 + b0 + 2 * stream, pol);
    const float4 a3 = ldg_stream(xa4 + b0 + 3 * stream, pol);
    const float4 s0 = ldg_stream(xs4 + b0,              pol);
    const float4 s1 = ldg_stream(xs4 + b0 +     stream, pol);
    const float4 s2 = ldg_stream(xs4 + b0 + 2 * stream, pol);
    const float4 s3 = ldg_stream(xs4 + b0 + 3 * stream, pol);

    float pa0 = a0.x * wa.x + a0.y * wa.y + a0.z * wa.z + a0.w * wa.w;
    float pa1 = a1.x * wa.x + a1.y * wa.y + a1.z * wa.z + a1.w * wa.w;
    float pa2 = a2.x * wa.x + a2.y * wa.y + a2.z * wa.z + a2.w * wa.w;
    float pa3 = a3.x * wa.x + a3.y * wa.y + a3.z * wa.z + a3.w * wa.w;
    float ps0 = s0.x * ws.x + s0.y * ws.y + s0.z * ws.z + s0.w * ws.w;
    float ps1 = s1.x * ws.x + s1.y * ws.y + s1.z * ws.z + s1.w * ws.w;
    float ps2 = s2.x * ws.x + s2.y * ws.y + s2.z * ws.z + s2.w * ws.w;
    float ps3 = s3.x * ws.x + s3.y * ws.y + s3.z * ws.z + s3.w * ws.w;

    #pragma unroll
    for (int off = 8; off > 0; off >>= 1) {
        pa0 += __shfl_xor_sync(0xFFFFFFFFu, pa0, off);
        ps0 += __shfl_xor_sync(0xFFFFFFFFu, ps0, off);
        pa1 += __shfl_xor_sync(0xFFFFFFFFu, pa1, off);
        ps1 += __shfl_xor_sync(0xFFFFFFFFu, ps1, off);
        pa2 += __shfl_xor_sync(0xFFFFFFFFu, pa2, off);
        ps2 += __shfl_xor_sync(0xFFFFFFFFu, ps2, off);
        pa3 += __shfl_xor_sync(0xFFFFFFFFu, pa3, off);
        ps3 += __shfl_xor_sync(0xFFFFFFFFu, ps3, off);
    }

    if (lane16 == 0) {
        const float ba = __ldg(b_act);
        const float bs = __ldg(b_saut);
        const float w2 = __ldg(W2);
        const float bb = __ldg(b2);

        {
            const float xs = ps0 + bs;
            float h = (pa0 + ba) + xs;
            h = (h >= 0.0f) ? h : NEG_SLOPE * h;
            stg_stream(out + k, xs / (1.0f + __expf(-(h * w2 + bb))), pol);
        }
        {
            const float xs = ps1 + bs;
            float h = (pa1 + ba) + xs;
            h = (h >= 0.0f) ? h : NEG_SLOPE * h;
            stg_stream(out + k + q, xs / (1.0f + __expf(-(h * w2 + bb))), pol);
        }
        {
            const float xs = ps2 + bs;
            float h = (pa2 + ba) + xs;
            h = (h >= 0.0f) ? h : NEG_SLOPE * h;
            stg_stream(out + k + 2 * q, xs / (1.0f + __expf(-(h * w2 + bb))), pol);
        }
        {
            const float xs = ps3 + bs;
            float h = (pa3 + ba) + xs;
            h = (h >= 0.0f) ? h : NEG_SLOPE * h;
            stg_stream(out + k + 3 * q, xs / (1.0f + __expf(-(h * w2 + bb))), pol);
        }
    }
}

extern "C" void kernel_launch(void* const* d_in, const int* in_sizes, int n_in,
                              void* d_out, int out_size)
{
    const float* xatt   = (const float*)d_in[0];
    const float* xsaut  = (const float*)d_in[1];
    const float* W_act  = (const float*)d_in[2];
    const float* b_act  = (const float*)d_in[3];
    const float* W_saut = (const float*)d_in[4];
    const float* b_saut = (const float*)d_in[5];
    const float* W2     = (const float*)d_in[6];
    const float* b2     = (const float*)d_in[7];
    float* out = (float*)d_out;

    const int q = out_size / 4;              // 262,144
    const int threads = 256;
    const long long total_threads = (long long)q * 16;
    const int blocks = (int)((total_threads + threads - 1) / threads);

    attn_gate_kernel<<<blocks, threads>>>(xatt, xsaut, W_act, b_act,
                                          W_saut, b_saut, W2, b2,
                                          out, q);
}